// round 9
// baseline (speedup 1.0000x reference)
#include <cuda_runtime.h>
#include <cstdint>
#include <cstddef>

#define BATCH 8192
#define INF   784
#define HID   4096
#define OUTF  10
#define KP    832            // 13 chunks of 64
#define NCH   13

#define TMT 128
#define TNT 128
#define NTHR 544             // 16 consumer warps + 1 producer warp
#define NTILES 2048          // (HID/TNT)*(BATCH/TMT) = 32*64
#define MT_CNT 64            // BATCH/TMT

// x = a1/16 + a2/4064 + eps, |eps| <= 1/8128
#define S1_INV 0.0625f
#define S2_INV (1.0f / 4064.0f)

// chunk-major gmem blocks
#define CHUNK_A (BATCH * 64)
#define CHUNK_B (HID * 64)

// SMEM: 5 stages x (Ahi 8K | Alo 8K | B 8K) + Qb + W2 + b1 + bars
#define STAGE_B   24576u
#define NSTG      5
#define SOFF_QB   122880u            // [4 wn][128][10] f32 = 20480
#define SOFF_W2   143360u            // [10][128] f32 = 5120
#define SOFF_B1   148480u            // [128] f32
#define SOFF_FBAR 148992u            // full[5]
#define SOFF_EBAR 149032u            // empty[5]
#define SMEM_DYN  149504u

// consumer-only named barrier (16 warps = 512 threads)
#define CONS_BAR() asm volatile("bar.sync 1, 512;" ::: "memory")

// ---------------------------------------------------------------------------
__device__ signed char g_A8c[2ull * NCH * CHUNK_A];
__device__ signed char g_S8c[(size_t)NCH * CHUNK_B];
__device__ float g_part[32ull * BATCH * OUTF];

// ---------------------------------------------------------------------------
__device__ __forceinline__ uint32_t smem_u32(const void* p) {
    uint32_t a;
    asm("{ .reg .u64 t; cvta.to.shared.u64 t, %1; cvt.u32.u64 %0, t; }"
        : "=r"(a) : "l"(p));
    return a;
}

__device__ __forceinline__ uint32_t chunk_off(int row, int kk) {
    uint32_t line = (uint32_t)(row >> 1);
    uint32_t col  = (((uint32_t)(row & 1)) << 6) | (uint32_t)kk;
    return (line << 7) | (col ^ ((line & 7u) << 4));
}

__device__ __forceinline__ void ldsm_x4(uint32_t& r0, uint32_t& r1,
                                        uint32_t& r2, uint32_t& r3, uint32_t a) {
    asm volatile("ldmatrix.sync.aligned.m8n8.x4.shared.b16 {%0,%1,%2,%3}, [%4];"
                 : "=r"(r0), "=r"(r1), "=r"(r2), "=r"(r3) : "r"(a));
}

__device__ __forceinline__ void mma_s8(int* d, uint32_t a0, uint32_t a1,
                                       uint32_t a2, uint32_t a3,
                                       uint32_t b0, uint32_t b1) {
    asm volatile(
        "mma.sync.aligned.m16n8k32.row.col.s32.s8.s8.s32 "
        "{%0,%1,%2,%3}, {%4,%5,%6,%7}, {%8,%9}, {%0,%1,%2,%3};"
        : "+r"(d[0]), "+r"(d[1]), "+r"(d[2]), "+r"(d[3])
        : "r"(a0), "r"(a1), "r"(a2), "r"(a3), "r"(b0), "r"(b1));
}

#define MBAR_INIT(a, c) \
    asm volatile("mbarrier.init.shared.b64 [%0], %1;" :: "r"(a), "r"(c) : "memory")
#define MBAR_EXPECT(a, bytes) \
    asm volatile("mbarrier.arrive.expect_tx.shared.b64 _, [%0], %1;" \
                 :: "r"(a), "r"(bytes) : "memory")
#define MBAR_ARRIVE(a) \
    asm volatile("mbarrier.arrive.shared.b64 _, [%0];" :: "r"(a) : "memory")
#define BULK_CP(dst, src, size, mbar) \
    asm volatile("cp.async.bulk.shared::cluster.global.mbarrier::complete_tx::bytes " \
                 "[%0], [%1], %2, [%3];" \
                 :: "r"(dst), "l"(src), "r"(size), "r"(mbar) : "memory")

#define MBAR_WAIT(a, par) do {                                                 \
    uint32_t _m = (a), _p = (par), _d;                                         \
    asm volatile("{\n\t.reg .pred p;\n\t"                                      \
        "mbarrier.try_wait.parity.acquire.cta.shared::cta.b64 p, [%1], %2;\n\t"\
        "selp.b32 %0, 1, 0, p;\n\t}" : "=r"(_d) : "r"(_m), "r"(_p) : "memory");\
    if (!_d) {                                                                 \
        asm volatile("{\n\t.reg .pred P1;\n\t"                                 \
            "WL_%=:\n\t"                                                       \
            "mbarrier.try_wait.parity.acquire.cta.shared::cta.b64 P1, [%0], %1, 0x989680;\n\t" \
            "@P1 bra.uni WD_%=;\n\t"                                           \
            "bra.uni WL_%=;\n\t"                                               \
            "WD_%=:\n\t}" :: "r"(_m), "r"(_p) : "memory");                     \
    }                                                                          \
} while (0)

// ---------------------------------------------------------------------------
__global__ void prep_x_kernel(const float* __restrict__ x) {
    int idx = blockIdx.x * blockDim.x + threadIdx.x;
    if (idx >= BATCH * KP) return;
    int m = idx / KP, k = idx - m * KP;
    float v = (k < INF) ? x[m * INF + k] : 0.0f;
    float a1 = rintf(v * 16.0f);
    float r  = v - a1 * S1_INV;
    float a2 = rintf(r * 4064.0f);
    int c = k >> 6, kk = k & 63;
    size_t o = (size_t)c * CHUNK_A + chunk_off(m, kk);
    g_A8c[o] = (signed char)(int)a1;
    g_A8c[(size_t)NCH * CHUNK_A + o] = (signed char)(int)a2;
}

__global__ void prep_w_kernel(const float* __restrict__ W1) {
    int idx = blockIdx.x * blockDim.x + threadIdx.x;
    if (idx >= HID * KP) return;
    int r = idx / KP, k = idx - r * KP;
    float v = (k < INF) ? W1[r * INF + k] : 0.0f;
    int c = k >> 6, kk = k & 63;
    g_S8c[(size_t)c * CHUNK_B + chunk_off(r, kk)] =
        (signed char)((v > 0.0f) ? 1 : ((v < 0.0f) ? -1 : 0));
}

// ---------------------------------------------------------------------------
// GEMM1: PERSISTENT warp-specialized kernel. 148 CTAs loop over 2048 tiles.
// Producer warp streams all chunks of all its tiles through a 5-stage ring
// that never drains; consumers MMA + shfl-based fused epilogue into Qb.
// ---------------------------------------------------------------------------
__global__ __launch_bounds__(NTHR, 1)
void gemm1_kernel(const float* __restrict__ b1g, const float* __restrict__ W2g) {
    extern __shared__ unsigned char smem[];
    float* Qb   = (float*)(smem + SOFF_QB);       // [4 wn][128][10]
    float* W2sh = (float*)(smem + SOFF_W2);
    float* b1sh = (float*)(smem + SOFF_B1);
    const uint32_t sb = smem_u32(smem);

    const int tid = threadIdx.x;
    const int wid = tid >> 5;
    const int lane = tid & 31;

    if (tid == 0) {
        #pragma unroll
        for (int s = 0; s < NSTG; s++) {
            MBAR_INIT(sb + SOFF_FBAR + s * 8, 1);    // producer expect_tx
            MBAR_INIT(sb + SOFF_EBAR + s * 8, 16);   // 16 consumer warps
        }
    }
    __syncthreads();   // single convergent CTA-wide sync (incl. producer warp)

    // ---------------- producer warp ---------------------------------------
    if (wid == 16) {
        if (lane == 0) {
            int q = 0;
            for (int tile = blockIdx.x; tile < NTILES; tile += gridDim.x) {
                const int mt = tile & (MT_CNT - 1);
                const int nt = tile >> 6;
                const int m0 = mt * TMT;
                const int n0 = nt * TNT;
                for (int c = 0; c < NCH; c++, q++) {
                    const int s  = q % NSTG;
                    const int qr = q / NSTG;
                    if (q >= NSTG)
                        MBAR_WAIT(sb + SOFF_EBAR + s * 8, (qr + 1) & 1);
                    const uint32_t stg = sb + (uint32_t)s * STAGE_B;
                    const uint32_t mb  = sb + SOFF_FBAR + s * 8;
                    MBAR_EXPECT(mb, STAGE_B);
                    const signed char* a0 = g_A8c + (size_t)c * CHUNK_A + (size_t)m0 * 64;
                    const signed char* a1 = g_A8c + (size_t)(NCH + c) * CHUNK_A + (size_t)m0 * 64;
                    const signed char* bb = g_S8c + (size_t)c * CHUNK_B + (size_t)n0 * 64;
                    BULK_CP(stg,          a0, 8192u, mb);
                    BULK_CP(stg + 8192u,  a1, 8192u, mb);
                    BULK_CP(stg + 16384u, bb, 8192u, mb);
                }
            }
        }
        return;
    }

    // ---------------- consumers (512 threads) -----------------------------
    const int wm = wid & 3;
    const int wn = wid >> 2;
    const int l15 = lane & 15;
    const int g  = lane >> 2;
    const int tg = lane & 3;

    uint32_t a_line[2][2], a_xm[2][2], a_c0[2][2];
    #pragma unroll
    for (int pl = 0; pl < 2; pl++)
        #pragma unroll
        for (int mf = 0; mf < 2; mf++) {
            int r = wm * 32 + mf * 16 + l15;
            a_line[pl][mf] = (uint32_t)pl * 8192u + (((uint32_t)r >> 1) << 7);
            a_xm[pl][mf]   = (((uint32_t)(r >> 1) & 7u) << 4);
            a_c0[pl][mf]   = (((uint32_t)r & 1u) << 6) | (((uint32_t)lane >> 4) << 4);
        }
    uint32_t b_line[2], b_xm[2], b_c0[2];
    #pragma unroll
    for (int np = 0; np < 2; np++) {
        int r = wn * 32 + np * 16 + ((lane >> 4) << 3) + (lane & 7);
        b_line[np] = 16384u + (((uint32_t)r >> 1) << 7);
        b_xm[np]   = (((uint32_t)(r >> 1) & 7u) << 4);
        b_c0[np]   = (((uint32_t)r & 1u) << 6) | ((((uint32_t)lane >> 3) & 1u) << 4);
    }

    int q = 0;
    for (int tile = blockIdx.x; tile < NTILES; tile += gridDim.x) {
        const int mt = tile & (MT_CNT - 1);
        const int nt = tile >> 6;
        const int m0 = mt * TMT;
        const int n0 = nt * TNT;

        // tile-start: load W2/b1 for this n-strip (guard vs prev epilogue)
        for (int i = tid; i < OUTF * 128; i += 512) {
            int o = i >> 7, n = i & 127;
            W2sh[o * 128 + n] = W2g[o * HID + n0 + n];
        }
        if (tid < 128) b1sh[tid] = b1g[n0 + tid];
        CONS_BAR();

        int acc[2][2][4][4];
        #pragma unroll
        for (int pl = 0; pl < 2; pl++)
            #pragma unroll
            for (int mf = 0; mf < 2; mf++)
                #pragma unroll
                for (int n8 = 0; n8 < 4; n8++)
                    #pragma unroll
                    for (int e = 0; e < 4; e++) acc[pl][mf][n8][e] = 0;

        // ---- mainloop over 13 chunks ----
        for (int c = 0; c < NCH; c++, q++) {
            const int s  = q % NSTG;
            const int qr = q / NSTG;
            MBAR_WAIT(sb + SOFF_FBAR + s * 8, qr & 1);
            const uint32_t stg = sb + (uint32_t)s * STAGE_B;

            #pragma unroll
            for (int kb = 0; kb < 64; kb += 32) {
                uint32_t b[8];
                ldsm_x4(b[0], b[1], b[2], b[3],
                        stg + b_line[0] + ((b_c0[0] + kb) ^ b_xm[0]));
                ldsm_x4(b[4], b[5], b[6], b[7],
                        stg + b_line[1] + ((b_c0[1] + kb) ^ b_xm[1]));
                #pragma unroll
                for (int pl = 0; pl < 2; pl++) {
                    #pragma unroll
                    for (int mf = 0; mf < 2; mf++) {
                        uint32_t a0, a1, a2, a3;
                        ldsm_x4(a0, a1, a2, a3,
                                stg + a_line[pl][mf] + ((a_c0[pl][mf] + kb) ^ a_xm[pl][mf]));
                        mma_s8(acc[pl][mf][0], a0, a1, a2, a3, b[0], b[1]);
                        mma_s8(acc[pl][mf][1], a0, a1, a2, a3, b[2], b[3]);
                        mma_s8(acc[pl][mf][2], a0, a1, a2, a3, b[4], b[5]);
                        mma_s8(acc[pl][mf][3], a0, a1, a2, a3, b[6], b[7]);
                    }
                }
            }
            if (lane == 0) MBAR_ARRIVE(sb + SOFF_EBAR + s * 8);
        }

        // ---- fused epilogue (registers + shfl; stages untouched) ----
        #pragma unroll
        for (int mf = 0; mf < 2; mf++) {
            float a2r[2][OUTF];
            #pragma unroll
            for (int r = 0; r < 2; r++)
                #pragma unroll
                for (int o = 0; o < OUTF; o++) a2r[r][o] = 0.0f;

            #pragma unroll
            for (int n8 = 0; n8 < 4; n8++) {
                const int* Ah = acc[0][mf][n8];
                const int* Al = acc[1][mf][n8];
                const int colb = wn * 32 + n8 * 8 + 2 * tg;
                float h00 = (float)Ah[0] * S1_INV + (float)Al[0] * S2_INV + b1sh[colb];
                float h01 = (float)Ah[1] * S1_INV + (float)Al[1] * S2_INV + b1sh[colb + 1];
                float h10 = (float)Ah[2] * S1_INV + (float)Al[2] * S2_INV + b1sh[colb];
                float h11 = (float)Ah[3] * S1_INV + (float)Al[3] * S2_INV + b1sh[colb + 1];
                h00 = fminf(1.0f, fmaxf(-1.0f, h00));
                h01 = fminf(1.0f, fmaxf(-1.0f, h01));
                h10 = fminf(1.0f, fmaxf(-1.0f, h10));
                h11 = fminf(1.0f, fmaxf(-1.0f, h11));
                #pragma unroll
                for (int o = 0; o < OUTF; o++) {
                    float w0 = W2sh[o * 128 + colb];
                    float w1 = W2sh[o * 128 + colb + 1];
                    a2r[0][o] += h00 * w0 + h01 * w1;
                    a2r[1][o] += h10 * w0 + h11 * w1;
                }
            }
            // reduce across tg (4 lanes) and write Qb
            #pragma unroll
            for (int r = 0; r < 2; r++) {
                #pragma unroll
                for (int o = 0; o < OUTF; o++) {
                    float v = a2r[r][o];
                    v += __shfl_xor_sync(0xFFFFFFFFu, v, 1);
                    v += __shfl_xor_sync(0xFFFFFFFFu, v, 2);
                    a2r[r][o] = v;
                }
            }
            if (tg == 0) {
                #pragma unroll
                for (int r = 0; r < 2; r++) {
                    int row = wm * 32 + mf * 16 + g + r * 8;
                    #pragma unroll
                    for (int o = 0; o < OUTF; o++)
                        Qb[(wn * 128 + row) * OUTF + o] = a2r[r][o];
                }
            }
        }
        CONS_BAR();

        // combine wn quarters, write one slice per n-strip
        for (int i = tid; i < 128 * OUTF; i += 512) {
            float s = Qb[i] + Qb[128 * OUTF + i] + Qb[256 * OUTF + i] + Qb[384 * OUTF + i];
            int row = i / OUTF, o = i - row * OUTF;
            g_part[((size_t)nt * BATCH + m0 + row) * OUTF + o] = s;
        }
        // next tile's W2 load is guarded by the tile-start CONS_BAR
    }
}

// ---------------------------------------------------------------------------
__global__ void reduce_kernel(const float* __restrict__ b2, float* __restrict__ out) {
    int idx = blockIdx.x * blockDim.x + threadIdx.x;
    if (idx >= BATCH * OUTF) return;
    int o = idx % OUTF;
    float s = b2[o];
    #pragma unroll
    for (int p = 0; p < 32; p++)
        s += g_part[(size_t)p * BATCH * OUTF + idx];
    out[idx] = s;
}

// ---------------------------------------------------------------------------
extern "C" void kernel_launch(void* const* d_in, const int* in_sizes, int n_in,
                              void* d_out, int out_size) {
    (void)in_sizes; (void)n_in; (void)out_size;
    const float* x  = (const float*)d_in[0];
    const float* W1 = (const float*)d_in[1];
    const float* b1 = (const float*)d_in[2];
    const float* W2 = (const float*)d_in[3];
    const float* b2 = (const float*)d_in[4];
    float* out = (float*)d_out;

    cudaFuncSetAttribute(gemm1_kernel,
                         cudaFuncAttributeMaxDynamicSharedMemorySize, SMEM_DYN);

    prep_x_kernel<<<(BATCH * KP + 255) / 256, 256>>>(x);
    prep_w_kernel<<<(HID * KP + 255) / 256, 256>>>(W1);
    gemm1_kernel<<<148, NTHR, SMEM_DYN>>>(b1, W2);
    reduce_kernel<<<(BATCH * OUTF + 255) / 256, 256>>>(b2, out);
}

// round 12
// speedup vs baseline: 1.5901x; 1.5901x over previous
#include <cuda_runtime.h>
#include <cstdint>
#include <cstddef>

#define BATCH 8192
#define INF   784
#define HID   4096
#define OUTF  10
#define KP    832            // 13 chunks of 64
#define NCH   13

#define TMT 128
#define TNT 128
#define NTHR 544             // 16 consumer warps + 1 producer warp

// x = a1/16 + a2/4064 + eps, |eps| <= 1/8128
#define S1_INV 0.0625f
#define S2_INV (1.0f / 4064.0f)

// chunk-major gmem blocks
#define CHUNK_A (BATCH * 64)
#define CHUNK_B (HID * 64)

// SMEM: 4 stages x (Ahi 8K | Alo 8K | B 8K) = 98304
#define STAGE_B  24576u
#define NSTG     4
#define SOFF_QB  69632u              // [4][128][10] f32 quarter partials (reuses stage rgn)
#define SOFF_W2  98304u              // [10][128] f32
#define SOFF_B1  103424u             // [128] f32
#define SOFF_FBAR 103936u            // full[4]
#define SOFF_EBAR 103968u            // empty[4]
#define SMEM_DYN 104960u

// consumer-only named barrier (16 warps = 512 threads)
#define CONS_BAR() asm volatile("bar.sync 1, 512;" ::: "memory")

// ---------------------------------------------------------------------------
__device__ signed char g_A8c[2ull * NCH * CHUNK_A];
__device__ signed char g_S8c[(size_t)NCH * CHUNK_B];
__device__ float g_part[32ull * BATCH * OUTF];

// ---------------------------------------------------------------------------
__device__ __forceinline__ uint32_t smem_u32(const void* p) {
    uint32_t a;
    asm("{ .reg .u64 t; cvta.to.shared.u64 t, %1; cvt.u32.u64 %0, t; }"
        : "=r"(a) : "l"(p));
    return a;
}

__device__ __forceinline__ uint32_t chunk_off(int row, int kk) {
    uint32_t line = (uint32_t)(row >> 1);
    uint32_t col  = (((uint32_t)(row & 1)) << 6) | (uint32_t)kk;
    return (line << 7) | (col ^ ((line & 7u) << 4));
}

__device__ __forceinline__ void ldsm_x4(uint32_t& r0, uint32_t& r1,
                                        uint32_t& r2, uint32_t& r3, uint32_t a) {
    asm volatile("ldmatrix.sync.aligned.m8n8.x4.shared.b16 {%0,%1,%2,%3}, [%4];"
                 : "=r"(r0), "=r"(r1), "=r"(r2), "=r"(r3) : "r"(a));
}

__device__ __forceinline__ void mma_s8(int* d, uint32_t a0, uint32_t a1,
                                       uint32_t a2, uint32_t a3,
                                       uint32_t b0, uint32_t b1) {
    asm volatile(
        "mma.sync.aligned.m16n8k32.row.col.s32.s8.s8.s32 "
        "{%0,%1,%2,%3}, {%4,%5,%6,%7}, {%8,%9}, {%0,%1,%2,%3};"
        : "+r"(d[0]), "+r"(d[1]), "+r"(d[2]), "+r"(d[3])
        : "r"(a0), "r"(a1), "r"(a2), "r"(a3), "r"(b0), "r"(b1));
}

#define MBAR_INIT(a, c) \
    asm volatile("mbarrier.init.shared.b64 [%0], %1;" :: "r"(a), "r"(c) : "memory")
#define MBAR_EXPECT(a, bytes) \
    asm volatile("mbarrier.arrive.expect_tx.shared.b64 _, [%0], %1;" \
                 :: "r"(a), "r"(bytes) : "memory")
#define MBAR_ARRIVE(a) \
    asm volatile("mbarrier.arrive.shared.b64 _, [%0];" :: "r"(a) : "memory")
#define BULK_CP(dst, src, size, mbar) \
    asm volatile("cp.async.bulk.shared::cluster.global.mbarrier::complete_tx::bytes " \
                 "[%0], [%1], %2, [%3];" \
                 :: "r"(dst), "l"(src), "r"(size), "r"(mbar) : "memory")

#define MBAR_WAIT(a, par) do {                                                 \
    uint32_t _m = (a), _p = (par), _d;                                         \
    asm volatile("{\n\t.reg .pred p;\n\t"                                      \
        "mbarrier.try_wait.parity.acquire.cta.shared::cta.b64 p, [%1], %2;\n\t"\
        "selp.b32 %0, 1, 0, p;\n\t}" : "=r"(_d) : "r"(_m), "r"(_p) : "memory");\
    if (!_d) {                                                                 \
        asm volatile("{\n\t.reg .pred P1;\n\t"                                 \
            "WL_%=:\n\t"                                                       \
            "mbarrier.try_wait.parity.acquire.cta.shared::cta.b64 P1, [%0], %1, 0x989680;\n\t" \
            "@P1 bra.uni WD_%=;\n\t"                                           \
            "bra.uni WL_%=;\n\t"                                               \
            "WD_%=:\n\t}" :: "r"(_m), "r"(_p) : "memory");                     \
    }                                                                          \
} while (0)

// ---------------------------------------------------------------------------
// Fused vectorized prep: float4 reads, u32 writes into swizzled chunk layout.
// First BATCH*KP/4 threads handle x (both planes); next HID*KP/4 handle W1.
// ---------------------------------------------------------------------------
#define XQ (BATCH * KP / 4)
#define WQ (HID * KP / 4)

__global__ void prep_kernel(const float* __restrict__ x,
                            const float* __restrict__ W1) {
    int idx = blockIdx.x * blockDim.x + threadIdx.x;
    if (idx < XQ) {
        const int m  = idx / (KP / 4);
        const int k4 = (idx - m * (KP / 4)) * 4;
        float4 v = make_float4(0.f, 0.f, 0.f, 0.f);
        if (k4 < INF) v = *reinterpret_cast<const float4*>(x + m * INF + k4);
        uint32_t p1 = 0, p2 = 0;
        const float* vv = &v.x;
        #pragma unroll
        for (int j = 0; j < 4; j++) {
            float a1 = rintf(vv[j] * 16.0f);
            float r  = vv[j] - a1 * S1_INV;
            float a2 = rintf(r * 4064.0f);
            p1 |= ((uint32_t)(uint8_t)(signed char)(int)a1) << (j * 8);
            p2 |= ((uint32_t)(uint8_t)(signed char)(int)a2) << (j * 8);
        }
        const int c = k4 >> 6, kk = k4 & 63;
        const size_t o = (size_t)c * CHUNK_A + chunk_off(m, kk);
        *reinterpret_cast<uint32_t*>(g_A8c + o) = p1;
        *reinterpret_cast<uint32_t*>(g_A8c + (size_t)NCH * CHUNK_A + o) = p2;
    } else if (idx < XQ + WQ) {
        const int j4 = idx - XQ;
        const int r  = j4 / (KP / 4);
        const int k4 = (j4 - r * (KP / 4)) * 4;
        float4 v = make_float4(0.f, 0.f, 0.f, 0.f);
        if (k4 < INF) v = *reinterpret_cast<const float4*>(W1 + r * INF + k4);
        uint32_t ps = 0;
        const float* vv = &v.x;
        #pragma unroll
        for (int j = 0; j < 4; j++) {
            int s = (vv[j] > 0.0f) ? 1 : ((vv[j] < 0.0f) ? -1 : 0);
            ps |= ((uint32_t)(uint8_t)(signed char)s) << (j * 8);
        }
        const int c = k4 >> 6, kk = k4 & 63;
        *reinterpret_cast<uint32_t*>(
            g_S8c + (size_t)c * CHUNK_B + chunk_off(r, kk)) = ps;
    }
}

// ---------------------------------------------------------------------------
// GEMM1 (byte-identical to the passing R8 kernel): warp-specialized,
// producer warp issues bulk copies then exits; consumers use named barrier 1.
// ---------------------------------------------------------------------------
__global__ __launch_bounds__(NTHR, 1)
void gemm1_kernel(const float* __restrict__ b1g, const float* __restrict__ W2g) {
    extern __shared__ unsigned char smem[];
    float* Csh  = (float*)smem;                   // epilogue reuse of stages
    float* Qb   = (float*)(smem + SOFF_QB);       // [4][128][10]
    float* W2sh = (float*)(smem + SOFF_W2);
    float* b1sh = (float*)(smem + SOFF_B1);
    const uint32_t sb = smem_u32(smem);

    const int tid = threadIdx.x;
    const int wid = tid >> 5;
    const int lane = tid & 31;
    const int m0 = blockIdx.y * TMT;
    const int n0 = blockIdx.x * TNT;

    if (tid == 0) {
        #pragma unroll
        for (int s = 0; s < NSTG; s++) {
            MBAR_INIT(sb + SOFF_FBAR + s * 8, 1);    // producer expect_tx
            MBAR_INIT(sb + SOFF_EBAR + s * 8, 16);   // 16 consumer warps
        }
    }
    for (int i = tid; i < OUTF * 128; i += NTHR) {
        int o = i / 128, n = i - o * 128;
        W2sh[o * 128 + n] = W2g[o * HID + n0 + n];
    }
    if (tid < 128) b1sh[tid] = b1g[n0 + tid];
    __syncthreads();   // single, convergent CTA-wide sync

    // ---------------- producer warp: issue everything, then exit ----------
    if (wid == 16) {
        if (lane == 0) {
            for (int c = 0; c < NCH; c++) {
                const int s = c & 3;
                if (c >= NSTG)
                    MBAR_WAIT(sb + SOFF_EBAR + s * 8, ((c >> 2) + 1) & 1);
                const uint32_t stg = sb + (uint32_t)s * STAGE_B;
                const uint32_t mb  = sb + SOFF_FBAR + s * 8;
                MBAR_EXPECT(mb, STAGE_B);
                const signed char* a0 = g_A8c + (size_t)c * CHUNK_A + (size_t)m0 * 64;
                const signed char* a1 = g_A8c + (size_t)(NCH + c) * CHUNK_A + (size_t)m0 * 64;
                const signed char* bb = g_S8c + (size_t)c * CHUNK_B + (size_t)n0 * 64;
                BULK_CP(stg,          a0, 8192u, mb);
                BULK_CP(stg + 8192u,  a1, 8192u, mb);
                BULK_CP(stg + 16384u, bb, 8192u, mb);
            }
        }
        return;
    }

    // ---------------- consumers (512 threads) -----------------------------
    const int wm = wid & 3;
    const int wn = wid >> 2;
    const int l15 = lane & 15;

    uint32_t a_line[2][2], a_xm[2][2], a_c0[2][2];
    #pragma unroll
    for (int pl = 0; pl < 2; pl++)
        #pragma unroll
        for (int mf = 0; mf < 2; mf++) {
            int r = wm * 32 + mf * 16 + l15;
            a_line[pl][mf] = (uint32_t)pl * 8192u + (((uint32_t)r >> 1) << 7);
            a_xm[pl][mf]   = (((uint32_t)(r >> 1) & 7u) << 4);
            a_c0[pl][mf]   = (((uint32_t)r & 1u) << 6) | (((uint32_t)lane >> 4) << 4);
        }
    uint32_t b_line[2], b_xm[2], b_c0[2];
    #pragma unroll
    for (int np = 0; np < 2; np++) {
        int r = wn * 32 + np * 16 + ((lane >> 4) << 3) + (lane & 7);
        b_line[np] = 16384u + (((uint32_t)r >> 1) << 7);
        b_xm[np]   = (((uint32_t)(r >> 1) & 7u) << 4);
        b_c0[np]   = (((uint32_t)r & 1u) << 6) | ((((uint32_t)lane >> 3) & 1u) << 4);
    }

    int acc[2][2][4][4];
    #pragma unroll
    for (int pl = 0; pl < 2; pl++)
        #pragma unroll
        for (int mf = 0; mf < 2; mf++)
            #pragma unroll
            for (int n8 = 0; n8 < 4; n8++)
                #pragma unroll
                for (int e = 0; e < 4; e++) acc[pl][mf][n8][e] = 0;

    for (int c = 0; c < NCH; c++) {
        const int s = c & 3;
        MBAR_WAIT(sb + SOFF_FBAR + s * 8, (c >> 2) & 1);
        const uint32_t stg = sb + (uint32_t)s * STAGE_B;

        #pragma unroll
        for (int kb = 0; kb < 64; kb += 32) {
            uint32_t b[8];
            ldsm_x4(b[0], b[1], b[2], b[3],
                    stg + b_line[0] + ((b_c0[0] + kb) ^ b_xm[0]));
            ldsm_x4(b[4], b[5], b[6], b[7],
                    stg + b_line[1] + ((b_c0[1] + kb) ^ b_xm[1]));
            #pragma unroll
            for (int pl = 0; pl < 2; pl++) {
                #pragma unroll
                for (int mf = 0; mf < 2; mf++) {
                    uint32_t a0, a1, a2, a3;
                    ldsm_x4(a0, a1, a2, a3,
                            stg + a_line[pl][mf] + ((a_c0[pl][mf] + kb) ^ a_xm[pl][mf]));
                    mma_s8(acc[pl][mf][0], a0, a1, a2, a3, b[0], b[1]);
                    mma_s8(acc[pl][mf][1], a0, a1, a2, a3, b[2], b[3]);
                    mma_s8(acc[pl][mf][2], a0, a1, a2, a3, b[4], b[5]);
                    mma_s8(acc[pl][mf][3], a0, a1, a2, a3, b[6], b[7]);
                }
            }
        }
        if (lane == 0) MBAR_ARRIVE(sb + SOFF_EBAR + s * 8);
    }

    CONS_BAR();   // all stages consumed; no bulk copies in flight -> reuse as Csh

    // ---- combine planes in registers, store h tile to smem ----
    {
        const int g  = lane >> 2;
        const int tg = lane & 3;
        #pragma unroll
        for (int mf = 0; mf < 2; mf++) {
            #pragma unroll
            for (int n8 = 0; n8 < 4; n8++) {
                const int* Ah = acc[0][mf][n8];
                const int* Al = acc[1][mf][n8];
                int row0 = wm * 32 + mf * 16 + g;
                int col  = wn * 32 + n8 * 8 + 2 * tg;
                Csh[row0 * 132 + col]           = (float)Ah[0] * S1_INV + (float)Al[0] * S2_INV;
                Csh[row0 * 132 + col + 1]       = (float)Ah[1] * S1_INV + (float)Al[1] * S2_INV;
                Csh[(row0 + 8) * 132 + col]     = (float)Ah[2] * S1_INV + (float)Al[2] * S2_INV;
                Csh[(row0 + 8) * 132 + col + 1] = (float)Ah[3] * S1_INV + (float)Al[3] * S2_INV;
            }
        }
    }
    CONS_BAR();

    // ---- bias + clip + W2 contraction; quarter partials in smem ----
    {
        const int row = tid & 127;
        const int q   = tid >> 7;          // 0..3
        float a[OUTF];
        #pragma unroll
        for (int o = 0; o < OUTF; o++) a[o] = 0.0f;

        const int nbeg = q * 32;
        #pragma unroll 4
        for (int n = nbeg; n < nbeg + 32; n++) {
            float h = Csh[row * 132 + n] + b1sh[n];
            h = fminf(1.0f, fmaxf(-1.0f, h));
            #pragma unroll
            for (int o = 0; o < OUTF; o++) a[o] += h * W2sh[o * 128 + n];
        }
        #pragma unroll
        for (int o = 0; o < OUTF; o++)
            Qb[(q * 128 + row) * OUTF + o] = a[o];
    }
    CONS_BAR();

    // ---- combine quarters, write one slice per CTA column ----
    for (int i = tid; i < 128 * OUTF; i += 512) {
        float s = Qb[i] + Qb[128 * OUTF + i] + Qb[256 * OUTF + i] + Qb[384 * OUTF + i];
        int row = i / OUTF, o = i - row * OUTF;
        g_part[((size_t)blockIdx.x * BATCH + m0 + row) * OUTF + o] = s;
    }
}

// ---------------------------------------------------------------------------
// Vectorized reduce: float4 per thread over 32 slices.
// ---------------------------------------------------------------------------
__global__ void reduce_kernel(const float* __restrict__ b2, float* __restrict__ out) {
    int t = blockIdx.x * blockDim.x + threadIdx.x;
    if (t >= BATCH * OUTF / 4) return;
    int idx4 = t * 4;
    float4 s = make_float4(0.f, 0.f, 0.f, 0.f);
    #pragma unroll
    for (int p = 0; p < 32; p++) {
        const float4 v = *reinterpret_cast<const float4*>(
            g_part + (size_t)p * BATCH * OUTF + idx4);
        s.x += v.x; s.y += v.y; s.z += v.z; s.w += v.w;
    }
    s.x += b2[idx4 % OUTF];
    s.y += b2[(idx4 + 1) % OUTF];
    s.z += b2[(idx4 + 2) % OUTF];
    s.w += b2[(idx4 + 3) % OUTF];
    *reinterpret_cast<float4*>(out + idx4) = s;
}

// ---------------------------------------------------------------------------
extern "C" void kernel_launch(void* const* d_in, const int* in_sizes, int n_in,
                              void* d_out, int out_size) {
    (void)in_sizes; (void)n_in; (void)out_size;
    const float* x  = (const float*)d_in[0];
    const float* W1 = (const float*)d_in[1];
    const float* b1 = (const float*)d_in[2];
    const float* W2 = (const float*)d_in[3];
    const float* b2 = (const float*)d_in[4];
    float* out = (float*)d_out;

    cudaFuncSetAttribute(gemm1_kernel,
                         cudaFuncAttributeMaxDynamicSharedMemorySize, SMEM_DYN);

    prep_kernel<<<(XQ + WQ + 255) / 256, 256>>>(x, W1);
    gemm1_kernel<<<dim3(HID / TNT, BATCH / TMT), NTHR, SMEM_DYN>>>(b1, W2);
    reduce_kernel<<<(BATCH * OUTF / 4 + 255) / 256, 256>>>(b2, out);
}

// round 13
// speedup vs baseline: 1.7221x; 1.0830x over previous
#include <cuda_runtime.h>
#include <cstdint>
#include <cstddef>

#define BATCH 8192
#define INF   784
#define HID   4096
#define OUTF  10
#define KP    832            // 13 chunks of 64
#define NCH   13

#define TMT 128
#define TNT 128
#define NTHR 544             // 16 consumer warps + 1 producer warp

// x = a1/16 + a2/4064 + eps, |eps| <= 1/8128
#define S1_INV 0.0625f
#define S2_INV (1.0f / 4064.0f)

// chunk-major gmem blocks
#define CHUNK_A (BATCH * 64)
#define CHUNK_B (HID * 64)

// SMEM: 4 stages x (Ahi 8K | Alo 8K | B 8K) = 98304
#define STAGE_B  24576u
#define NSTG     4
#define SOFF_QB  69632u              // [4][128][10] f32 quarter partials (reuses stage rgn)
#define SOFF_W2  98304u              // [10][128] f32
#define SOFF_B1  103424u             // [128] f32
#define SOFF_FBAR 103936u            // full[4]
#define SOFF_EBAR 103968u            // empty[4]
#define SMEM_DYN 104960u

// consumer-only named barrier (16 warps = 512 threads)
#define CONS_BAR() asm volatile("bar.sync 1, 512;" ::: "memory")

// ---------------------------------------------------------------------------
__device__ signed char g_A8c[2ull * NCH * CHUNK_A];
__device__ signed char g_S8c[(size_t)NCH * CHUNK_B];
__device__ float g_part[32ull * BATCH * OUTF];

// ---------------------------------------------------------------------------
__device__ __forceinline__ uint32_t smem_u32(const void* p) {
    uint32_t a;
    asm("{ .reg .u64 t; cvta.to.shared.u64 t, %1; cvt.u32.u64 %0, t; }"
        : "=r"(a) : "l"(p));
    return a;
}

__device__ __forceinline__ uint32_t chunk_off(int row, int kk) {
    uint32_t line = (uint32_t)(row >> 1);
    uint32_t col  = (((uint32_t)(row & 1)) << 6) | (uint32_t)kk;
    return (line << 7) | (col ^ ((line & 7u) << 4));
}

__device__ __forceinline__ void ldsm_x4(uint32_t& r0, uint32_t& r1,
                                        uint32_t& r2, uint32_t& r3, uint32_t a) {
    asm volatile("ldmatrix.sync.aligned.m8n8.x4.shared.b16 {%0,%1,%2,%3}, [%4];"
                 : "=r"(r0), "=r"(r1), "=r"(r2), "=r"(r3) : "r"(a));
}

__device__ __forceinline__ void mma_s8(int* d, uint32_t a0, uint32_t a1,
                                       uint32_t a2, uint32_t a3,
                                       uint32_t b0, uint32_t b1) {
    asm volatile(
        "mma.sync.aligned.m16n8k32.row.col.s32.s8.s8.s32 "
        "{%0,%1,%2,%3}, {%4,%5,%6,%7}, {%8,%9}, {%0,%1,%2,%3};"
        : "+r"(d[0]), "+r"(d[1]), "+r"(d[2]), "+r"(d[3])
        : "r"(a0), "r"(a1), "r"(a2), "r"(a3), "r"(b0), "r"(b1));
}

#define MBAR_INIT(a, c) \
    asm volatile("mbarrier.init.shared.b64 [%0], %1;" :: "r"(a), "r"(c) : "memory")
#define MBAR_EXPECT(a, bytes) \
    asm volatile("mbarrier.arrive.expect_tx.shared.b64 _, [%0], %1;" \
                 :: "r"(a), "r"(bytes) : "memory")
#define MBAR_ARRIVE(a) \
    asm volatile("mbarrier.arrive.shared.b64 _, [%0];" :: "r"(a) : "memory")
#define BULK_CP(dst, src, size, mbar) \
    asm volatile("cp.async.bulk.shared::cluster.global.mbarrier::complete_tx::bytes " \
                 "[%0], [%1], %2, [%3];" \
                 :: "r"(dst), "l"(src), "r"(size), "r"(mbar) : "memory")

#define MBAR_WAIT(a, par) do {                                                 \
    uint32_t _m = (a), _p = (par), _d;                                         \
    asm volatile("{\n\t.reg .pred p;\n\t"                                      \
        "mbarrier.try_wait.parity.acquire.cta.shared::cta.b64 p, [%1], %2;\n\t"\
        "selp.b32 %0, 1, 0, p;\n\t}" : "=r"(_d) : "r"(_m), "r"(_p) : "memory");\
    if (!_d) {                                                                 \
        asm volatile("{\n\t.reg .pred P1;\n\t"                                 \
            "WL_%=:\n\t"                                                       \
            "mbarrier.try_wait.parity.acquire.cta.shared::cta.b64 P1, [%0], %1, 0x989680;\n\t" \
            "@P1 bra.uni WD_%=;\n\t"                                           \
            "bra.uni WL_%=;\n\t"                                               \
            "WD_%=:\n\t}" :: "r"(_m), "r"(_p) : "memory");                     \
    }                                                                          \
} while (0)

// ---------------------------------------------------------------------------
// Fused prep at 16-byte granularity: 4x float4 loads, uint4 swizzled stores.
// k16 is 16-aligned; swizzle XOR touches only bits [4:6] so 16B stay contiguous.
// 784 % 16 == 0, so each 16-wide group is either fully valid or fully padding.
// ---------------------------------------------------------------------------
#define XQ16 (BATCH * (KP / 16))
#define WQ16 (HID * (KP / 16))

__global__ void prep_kernel(const float* __restrict__ x,
                            const float* __restrict__ W1) {
    int idx = blockIdx.x * blockDim.x + threadIdx.x;
    if (idx < XQ16) {
        const int m   = idx / (KP / 16);
        const int k16 = (idx - m * (KP / 16)) * 16;
        uint4 p1 = make_uint4(0u, 0u, 0u, 0u);
        uint4 p2 = make_uint4(0u, 0u, 0u, 0u);
        if (k16 < INF) {
            uint32_t* w1 = &p1.x;
            uint32_t* w2 = &p2.x;
            #pragma unroll
            for (int q = 0; q < 4; q++) {
                const float4 v = *reinterpret_cast<const float4*>(
                    x + m * INF + k16 + q * 4);
                const float* vv = &v.x;
                uint32_t b1w = 0, b2w = 0;
                #pragma unroll
                for (int j = 0; j < 4; j++) {
                    float a1 = rintf(vv[j] * 16.0f);
                    float r  = vv[j] - a1 * S1_INV;
                    float a2 = rintf(r * 4064.0f);
                    b1w |= ((uint32_t)(uint8_t)(signed char)(int)a1) << (j * 8);
                    b2w |= ((uint32_t)(uint8_t)(signed char)(int)a2) << (j * 8);
                }
                w1[q] = b1w;
                w2[q] = b2w;
            }
        }
        const int c = k16 >> 6, kk = k16 & 63;
        const size_t o = (size_t)c * CHUNK_A + chunk_off(m, kk);
        *reinterpret_cast<uint4*>(g_A8c + o) = p1;
        *reinterpret_cast<uint4*>(g_A8c + (size_t)NCH * CHUNK_A + o) = p2;
    } else if (idx < XQ16 + WQ16) {
        const int j16 = idx - XQ16;
        const int r   = j16 / (KP / 16);
        const int k16 = (j16 - r * (KP / 16)) * 16;
        uint4 ps = make_uint4(0u, 0u, 0u, 0u);
        if (k16 < INF) {
            uint32_t* w = &ps.x;
            #pragma unroll
            for (int q = 0; q < 4; q++) {
                const float4 v = *reinterpret_cast<const float4*>(
                    W1 + r * INF + k16 + q * 4);
                const float* vv = &v.x;
                uint32_t bw = 0;
                #pragma unroll
                for (int j = 0; j < 4; j++) {
                    int s = (vv[j] > 0.0f) ? 1 : ((vv[j] < 0.0f) ? -1 : 0);
                    bw |= ((uint32_t)(uint8_t)(signed char)s) << (j * 8);
                }
                w[q] = bw;
            }
        }
        const int c = k16 >> 6, kk = k16 & 63;
        *reinterpret_cast<uint4*>(
            g_S8c + (size_t)c * CHUNK_B + chunk_off(r, kk)) = ps;
    }
}

// ---------------------------------------------------------------------------
// GEMM1: identical to passing R12 except the LAST chunk runs only kb=0 —
// k 784..831 is exact zero padding, so the kb=32 pass of chunk 12 is a no-op
// and skipping it is bitwise identical (saves 1/26 of all MMA instructions).
// ---------------------------------------------------------------------------
__global__ __launch_bounds__(NTHR, 1)
void gemm1_kernel(const float* __restrict__ b1g, const float* __restrict__ W2g) {
    extern __shared__ unsigned char smem[];
    float* Csh  = (float*)smem;                   // epilogue reuse of stages
    float* Qb   = (float*)(smem + SOFF_QB);       // [4][128][10]
    float* W2sh = (float*)(smem + SOFF_W2);
    float* b1sh = (float*)(smem + SOFF_B1);
    const uint32_t sb = smem_u32(smem);

    const int tid = threadIdx.x;
    const int wid = tid >> 5;
    const int lane = tid & 31;
    const int m0 = blockIdx.y * TMT;
    const int n0 = blockIdx.x * TNT;

    if (tid == 0) {
        #pragma unroll
        for (int s = 0; s < NSTG; s++) {
            MBAR_INIT(sb + SOFF_FBAR + s * 8, 1);    // producer expect_tx
            MBAR_INIT(sb + SOFF_EBAR + s * 8, 16);   // 16 consumer warps
        }
    }
    for (int i = tid; i < OUTF * 128; i += NTHR) {
        int o = i / 128, n = i - o * 128;
        W2sh[o * 128 + n] = W2g[o * HID + n0 + n];
    }
    if (tid < 128) b1sh[tid] = b1g[n0 + tid];
    __syncthreads();   // single, convergent CTA-wide sync

    // ---------------- producer warp: issue everything, then exit ----------
    if (wid == 16) {
        if (lane == 0) {
            for (int c = 0; c < NCH; c++) {
                const int s = c & 3;
                if (c >= NSTG)
                    MBAR_WAIT(sb + SOFF_EBAR + s * 8, ((c >> 2) + 1) & 1);
                const uint32_t stg = sb + (uint32_t)s * STAGE_B;
                const uint32_t mb  = sb + SOFF_FBAR + s * 8;
                MBAR_EXPECT(mb, STAGE_B);
                const signed char* a0 = g_A8c + (size_t)c * CHUNK_A + (size_t)m0 * 64;
                const signed char* a1 = g_A8c + (size_t)(NCH + c) * CHUNK_A + (size_t)m0 * 64;
                const signed char* bb = g_S8c + (size_t)c * CHUNK_B + (size_t)n0 * 64;
                BULK_CP(stg,          a0, 8192u, mb);
                BULK_CP(stg + 8192u,  a1, 8192u, mb);
                BULK_CP(stg + 16384u, bb, 8192u, mb);
            }
        }
        return;
    }

    // ---------------- consumers (512 threads) -----------------------------
    const int wm = wid & 3;
    const int wn = wid >> 2;
    const int l15 = lane & 15;

    uint32_t a_line[2][2], a_xm[2][2], a_c0[2][2];
    #pragma unroll
    for (int pl = 0; pl < 2; pl++)
        #pragma unroll
        for (int mf = 0; mf < 2; mf++) {
            int r = wm * 32 + mf * 16 + l15;
            a_line[pl][mf] = (uint32_t)pl * 8192u + (((uint32_t)r >> 1) << 7);
            a_xm[pl][mf]   = (((uint32_t)(r >> 1) & 7u) << 4);
            a_c0[pl][mf]   = (((uint32_t)r & 1u) << 6) | (((uint32_t)lane >> 4) << 4);
        }
    uint32_t b_line[2], b_xm[2], b_c0[2];
    #pragma unroll
    for (int np = 0; np < 2; np++) {
        int r = wn * 32 + np * 16 + ((lane >> 4) << 3) + (lane & 7);
        b_line[np] = 16384u + (((uint32_t)r >> 1) << 7);
        b_xm[np]   = (((uint32_t)(r >> 1) & 7u) << 4);
        b_c0[np]   = (((uint32_t)r & 1u) << 6) | ((((uint32_t)lane >> 3) & 1u) << 4);
    }

    int acc[2][2][4][4];
    #pragma unroll
    for (int pl = 0; pl < 2; pl++)
        #pragma unroll
        for (int mf = 0; mf < 2; mf++)
            #pragma unroll
            for (int n8 = 0; n8 < 4; n8++)
                #pragma unroll
                for (int e = 0; e < 4; e++) acc[pl][mf][n8][e] = 0;

    for (int c = 0; c < NCH; c++) {
        const int s = c & 3;
        MBAR_WAIT(sb + SOFF_FBAR + s * 8, (c >> 2) & 1);
        const uint32_t stg = sb + (uint32_t)s * STAGE_B;

        const int kbmax = (c == NCH - 1) ? 32 : 64;   // last chunk: k>=784 is zero
        #pragma unroll 2
        for (int kb = 0; kb < kbmax; kb += 32) {
            uint32_t b[8];
            ldsm_x4(b[0], b[1], b[2], b[3],
                    stg + b_line[0] + ((b_c0[0] + kb) ^ b_xm[0]));
            ldsm_x4(b[4], b[5], b[6], b[7],
                    stg + b_line[1] + ((b_c0[1] + kb) ^ b_xm[1]));
            #pragma unroll
            for (int pl = 0; pl < 2; pl++) {
                #pragma unroll
                for (int mf = 0; mf < 2; mf++) {
                    uint32_t a0, a1, a2, a3;
                    ldsm_x4(a0, a1, a2, a3,
                            stg + a_line[pl][mf] + ((a_c0[pl][mf] + kb) ^ a_xm[pl][mf]));
                    mma_s8(acc[pl][mf][0], a0, a1, a2, a3, b[0], b[1]);
                    mma_s8(acc[pl][mf][1], a0, a1, a2, a3, b[2], b[3]);
                    mma_s8(acc[pl][mf][2], a0, a1, a2, a3, b[4], b[5]);
                    mma_s8(acc[pl][mf][3], a0, a1, a2, a3, b[6], b[7]);
                }
            }
        }
        if (lane == 0) MBAR_ARRIVE(sb + SOFF_EBAR + s * 8);
    }

    CONS_BAR();   // all stages consumed; no bulk copies in flight -> reuse as Csh

    // ---- combine planes in registers, store h tile to smem ----
    {
        const int g  = lane >> 2;
        const int tg = lane & 3;
        #pragma unroll
        for (int mf = 0; mf < 2; mf++) {
            #pragma unroll
            for (int n8 = 0; n8 < 4; n8++) {
                const int* Ah = acc[0][mf][n8];
                const int* Al = acc[1][mf][n8];
                int row0 = wm * 32 + mf * 16 + g;
                int col  = wn * 32 + n8 * 8 + 2 * tg;
                Csh[row0 * 132 + col]           = (float)Ah[0] * S1_INV + (float)Al[0] * S2_INV;
                Csh[row0 * 132 + col + 1]       = (float)Ah[1] * S1_INV + (float)Al[1] * S2_INV;
                Csh[(row0 + 8) * 132 + col]     = (float)Ah[2] * S1_INV + (float)Al[2] * S2_INV;
                Csh[(row0 + 8) * 132 + col + 1] = (float)Ah[3] * S1_INV + (float)Al[3] * S2_INV;
            }
        }
    }
    CONS_BAR();

    // ---- bias + clip + W2 contraction; quarter partials in smem ----
    {
        const int row = tid & 127;
        const int q   = tid >> 7;          // 0..3
        float a[OUTF];
        #pragma unroll
        for (int o = 0; o < OUTF; o++) a[o] = 0.0f;

        const int nbeg = q * 32;
        #pragma unroll 4
        for (int n = nbeg; n < nbeg + 32; n++) {
            float h = Csh[row * 132 + n] + b1sh[n];
            h = fminf(1.0f, fmaxf(-1.0f, h));
            #pragma unroll
            for (int o = 0; o < OUTF; o++) a[o] += h * W2sh[o * 128 + n];
        }
        #pragma unroll
        for (int o = 0; o < OUTF; o++)
            Qb[(q * 128 + row) * OUTF + o] = a[o];
    }
    CONS_BAR();

    // ---- combine quarters, write one slice per CTA column ----
    for (int i = tid; i < 128 * OUTF; i += 512) {
        float s = Qb[i] + Qb[128 * OUTF + i] + Qb[256 * OUTF + i] + Qb[384 * OUTF + i];
        int row = i / OUTF, o = i - row * OUTF;
        g_part[((size_t)blockIdx.x * BATCH + m0 + row) * OUTF + o] = s;
    }
}

// ---------------------------------------------------------------------------
// Vectorized reduce: float4 per thread over 32 slices.
// ---------------------------------------------------------------------------
__global__ void reduce_kernel(const float* __restrict__ b2, float* __restrict__ out) {
    int t = blockIdx.x * blockDim.x + threadIdx.x;
    if (t >= BATCH * OUTF / 4) return;
    int idx4 = t * 4;
    float4 s = make_float4(0.f, 0.f, 0.f, 0.f);
    #pragma unroll
    for (int p = 0; p < 32; p++) {
        const float4 v = *reinterpret_cast<const float4*>(
            g_part + (size_t)p * BATCH * OUTF + idx4);
        s.x += v.x; s.y += v.y; s.z += v.z; s.w += v.w;
    }
    s.x += b2[idx4 % OUTF];
    s.y += b2[(idx4 + 1) % OUTF];
    s.z += b2[(idx4 + 2) % OUTF];
    s.w += b2[(idx4 + 3) % OUTF];
    *reinterpret_cast<float4*>(out + idx4) = s;
}

// ---------------------------------------------------------------------------
extern "C" void kernel_launch(void* const* d_in, const int* in_sizes, int n_in,
                              void* d_out, int out_size) {
    (void)in_sizes; (void)n_in; (void)out_size;
    const float* x  = (const float*)d_in[0];
    const float* W1 = (const float*)d_in[1];
    const float* b1 = (const float*)d_in[2];
    const float* W2 = (const float*)d_in[3];
    const float* b2 = (const float*)d_in[4];
    float* out = (float*)d_out;

    cudaFuncSetAttribute(gemm1_kernel,
                         cudaFuncAttributeMaxDynamicSharedMemorySize, SMEM_DYN);

    prep_kernel<<<(XQ16 + WQ16 + 255) / 256, 256>>>(x, W1);
    gemm1_kernel<<<dim3(HID / TNT, BATCH / TMT), NTHR, SMEM_DYN>>>(b1, W2);
    reduce_kernel<<<(BATCH * OUTF / 4 + 255) / 256, 256>>>(b2, out);
}